// round 1
// baseline (speedup 1.0000x reference)
#include <cuda_runtime.h>
#include <math.h>

#define BB 8
#define SS 4096
#define HH 4096
#define DD 128
#define NMAX 64
#define NT 32
#define HT (HH/NT)   /* 128 */

// Persistent scratch (allocation-free rule: __device__ globals)
__device__ int   g_pos[BB][NMAX];
__device__ int   g_count[BB];
__device__ float g_K[BB][NMAX][DD];
__device__ float g_Q[BB][DD];
__device__ float g_V[BB][NMAX];
__device__ float g_rew[BB];

// ---------------------------------------------------------------------------
// Kernel 1: per-batch mask scan -> sentence positions + counts; zero scratch.
// ---------------------------------------------------------------------------
__global__ void k_scan(const int* __restrict__ mask) {
    int b   = blockIdx.x;
    int tid = threadIdx.x;          // 256 threads
    int lane = tid & 31, warp = tid >> 5;

    int base = tid * 16;
    int v[16];
    int c = 0;
#pragma unroll
    for (int j = 0; j < 16; j++) {
        v[j] = mask[b * SS + base + j];
        c += (v[j] > 0);
    }
    // inclusive warp scan of per-thread counts
    int x = c;
#pragma unroll
    for (int off = 1; off < 32; off <<= 1) {
        int y = __shfl_up_sync(0xffffffffu, x, off);
        if (lane >= off) x += y;
    }
    __shared__ int wsum[8];
    __shared__ int woff[8];
    if (lane == 31) wsum[warp] = x;
    __syncthreads();
    if (tid == 0) {
        int a = 0;
        for (int w = 0; w < 8; w++) { woff[w] = a; a += wsum[w]; }
        g_count[b] = (a < NMAX) ? a : NMAX;
    }
    __syncthreads();

    int r = woff[warp] + x - c;     // exclusive prefix for this thread
#pragma unroll
    for (int j = 0; j < 16; j++) {
        if (v[j] > 0) {
            if (r < NMAX) g_pos[b][r] = base + j;
            r++;
        }
    }

    // zero accumulators (must happen every launch - graph replays)
    float* kp = &g_K[b][0][0];
    for (int i = tid; i < NMAX * DD; i += 256) kp[i] = 0.0f;
    if (tid < DD)   g_Q[b][tid] = 0.0f;
    if (tid < NMAX) g_V[b][tid] = 0.0f;
}

// ---------------------------------------------------------------------------
// Kernel 2: h-tiled projections at sentence rows only.
// grid = (NT, B), block = 256. Each block: batch b, h-slice [h0, h0+128).
// Wk slice lives in 64 registers/thread (read once per block).
// ---------------------------------------------------------------------------
__global__ void __launch_bounds__(256, 2)
k_proj(const float* __restrict__ hid,
       const float* __restrict__ Wq,
       const float* __restrict__ Wk,
       const float* __restrict__ Wr) {
    int b    = blockIdx.y;
    int tile = blockIdx.x;
    int h0   = tile * HT;
    int tid  = threadIdx.x;          // 256
    int d    = tid & (DD - 1);       // 0..127
    int half = tid >> 7;             // 0/1 -> h sub-range

    int cnt  = g_count[b];
    int last = cnt - 1;

    __shared__ float sh[HT];
    __shared__ float swr[HT];

    // preload this block's Wk slice into registers (64 per thread)
    float wk[HT / 2];
    const int hbase = h0 + half * (HT / 2);
#pragma unroll
    for (int j = 0; j < HT / 2; j++)
        wk[j] = Wk[(size_t)(hbase + j) * DD + d];

    if (tid < HT) swr[tid] = Wr[h0 + tid];

    for (int n = 0; n < cnt; n++) {
        int pos = g_pos[b][n];
        __syncthreads();             // protect sh reuse
        if (tid < HT)
            sh[tid] = hid[((size_t)b * SS + pos) * HH + h0 + tid];
        __syncthreads();

        const float* shh = &sh[half * (HT / 2)];
        float acc = 0.0f;
#pragma unroll
        for (int j = 0; j < HT / 2; j++)
            acc += shh[j] * wk[j];
        atomicAdd(&g_K[b][n][d], acc);

        if (n == last) {             // Q only needed at the last sentence row
            float aq = 0.0f;
#pragma unroll
            for (int j = 0; j < HT / 2; j++)
                aq += shh[j] * Wq[(size_t)(hbase + j) * DD + d];
            atomicAdd(&g_Q[b][d], aq);
        }

        if (half == 0) {             // V partial: warps 0-3 reduce 128 products
            float vp = sh[tid] * swr[tid];
#pragma unroll
            for (int off = 16; off; off >>= 1)
                vp += __shfl_down_sync(0xffffffffu, vp, off);
            if ((tid & 31) == 0) atomicAdd(&g_V[b][n], vp);
        }
    }
}

// ---------------------------------------------------------------------------
// Kernel 3: RoPE(rank) + logits + softmax + per-batch reward.
// grid = B, block = 128 (thread = head dim d).
// ---------------------------------------------------------------------------
__global__ void k_attn(const float* __restrict__ bq,
                       const float* __restrict__ bk,
                       const float* __restrict__ br) {
    int b = blockIdx.x;
    int tid = threadIdx.x, lane = tid & 31, warp = tid >> 5;
    int cnt = g_count[b];
    int last = cnt - 1;

    __shared__ float qs[DD];
    __shared__ float lg[NMAX];

    const float LN_THETA = 9.210340371976184f;   // ln(10000)

    // RoPE the single q row with angle (count-1)*freq
    {
        float freq = expf(-LN_THETA * (float)(2 * (tid >> 1)) / 128.0f);
        float qv = g_Q[b][tid] + bq[tid];
        float a = (float)last * freq;
        float cq = cosf(a), sq = sinf(a);
        float qp = __shfl_xor_sync(0xffffffffu, qv, 1);
        qs[tid] = ((tid & 1) == 0) ? (qv * cq - qp * sq) : (qp * sq + qv * cq);
    }
    __syncthreads();

    // each warp handles logits n = warp, warp+4, ...
    for (int n = warp; n < cnt; n += 4) {
        float dot = 0.0f;
#pragma unroll
        for (int s4 = 0; s4 < 4; s4++) {
            int d = lane + s4 * 32;
            float kv = g_K[b][n][d] + bk[d];
            float f = expf(-LN_THETA * (float)(2 * (d >> 1)) / 128.0f);
            float a = (float)n * f;
            float cn = cosf(a), sn = sinf(a);
            float kp = __shfl_xor_sync(0xffffffffu, kv, 1);
            float kr = ((d & 1) == 0) ? (kv * cn - kp * sn) : (kp * sn + kv * cn);
            dot += qs[d] * kr;
        }
#pragma unroll
        for (int off = 16; off; off >>= 1)
            dot += __shfl_xor_sync(0xffffffffu, dot, off);
        if (lane == 0) lg[n] = dot * 0.08838834764831845f;  // 1/sqrt(128)
    }
    __syncthreads();

    if (tid == 0) {
        float mx = -3.0e38f;
        for (int n = 0; n < cnt; n++) mx = fmaxf(mx, lg[n]);
        float sum = 0.0f, rew = 0.0f, prev = 0.0f;
        for (int n = 0; n < cnt; n++) {
            float e = expf(lg[n] - mx);
            float v = g_V[b][n] + br[0];
            rew += e * (v - prev);    // sr[n] = v[n] - v[n-1]
            sum += e;
            prev = v;
        }
        g_rew[b] = rew / sum;
    }
}

// ---------------------------------------------------------------------------
// Kernel 4: pairwise -log_sigmoid loss, write output.
// ---------------------------------------------------------------------------
__global__ void k_loss(float* __restrict__ out, int out_size) {
    if (threadIdx.x == 0 && blockIdx.x == 0) {
        float loss = 0.0f;
#pragma unroll
        for (int i = 0; i < 4; i++) {
            float x = g_rew[i] - g_rew[i + 4];
            // -log_sigmoid(x), numerically stable
            loss += (x >= 0.0f) ? log1pf(expf(-x)) : (-x + log1pf(expf(x)));
        }
        loss *= 0.25f;
        if (out_size >= 9) {
            out[0] = loss;
            for (int i = 0; i < 8; i++) out[1 + i] = g_rew[i];
        } else if (out_size == 8) {
            for (int i = 0; i < 8; i++) out[i] = g_rew[i];
        } else {
            out[0] = loss;
        }
    }
}

// ---------------------------------------------------------------------------
extern "C" void kernel_launch(void* const* d_in, const int* in_sizes, int n_in,
                              void* d_out, int out_size) {
    const float* hid  = (const float*)d_in[0];
    const int*   mask = (const int*)  d_in[1];
    const float* Wq   = (const float*)d_in[2];
    const float* bq   = (const float*)d_in[3];
    const float* Wk   = (const float*)d_in[4];
    const float* bk   = (const float*)d_in[5];
    const float* Wr   = (const float*)d_in[6];
    const float* br   = (const float*)d_in[7];
    float* out = (float*)d_out;

    k_scan<<<BB, 256>>>(mask);
    k_proj<<<dim3(NT, BB), 256>>>(hid, Wq, Wk, Wr);
    k_attn<<<BB, 128>>>(bq, bk, br);
    k_loss<<<1, 32>>>(out, out_size);
}

// round 3
// speedup vs baseline: 1.0667x; 1.0667x over previous
#include <cuda_runtime.h>
#include <math.h>

#define BB 8
#define SS 4096
#define HH 4096
#define DD 128
#define NMAX 64
#define NT 64
#define HT 64            /* HH / NT */
#define TPB 128

// -------- persistent scratch (exclusive writes -> no zeroing, no atomics) ---
__device__ float g_Kp[BB][NT][NMAX][DD];   // 16 MB of K partials
__device__ float g_Qp[BB][NT][DD];
__device__ float g_Vp[BB][NMAX][NT * 2];
__device__ float g_K[BB][NMAX][DD];
__device__ float g_Q[BB][DD];
__device__ float g_V[BB][NMAX];

// ---------------------------------------------------------------------------
// Kernel 1: projections at sentence rows. grid=(NT,B), 128 threads.
// Inline mask scan; all rows preloaded to smem; Wk slice in f32x2 registers.
// ---------------------------------------------------------------------------
__global__ void __launch_bounds__(TPB)
k_proj(const float* __restrict__ hid,
       const int*   __restrict__ mask,
       const float* __restrict__ Wq,
       const float* __restrict__ Wk,
       const float* __restrict__ Wr) {
    const int b    = blockIdx.y;
    const int tile = blockIdx.x;
    const int h0   = tile * HT;
    const int tid  = threadIdx.x;
    const int lane = tid & 31, warp = tid >> 5;

    // 16B-aligned FIRST so vector LDS/STS are legal
    __shared__ __align__(16) float sh[NMAX * HT];   // 16 KB
    __shared__ float swr[HT];
    __shared__ int   s_pos[NMAX];
    __shared__ int   s_wsum[4];
    __shared__ int   s_base;

    // ---- inline scan: 2 passes over globally-contiguous halves ----
    if (tid == 0) s_base = 0;
    __syncthreads();
    const int* mrow = mask + b * SS;
    for (int pass = 0; pass < 2; pass++) {
        int base = pass * (SS / 2) + tid * 16;
        int v[16];
        int c = 0;
#pragma unroll
        for (int j = 0; j < 16; j++) { v[j] = mrow[base + j]; c += (v[j] > 0); }
        int x = c;
#pragma unroll
        for (int off = 1; off < 32; off <<= 1) {
            int y = __shfl_up_sync(0xffffffffu, x, off);
            if (lane >= off) x += y;
        }
        if (lane == 31) s_wsum[warp] = x;
        __syncthreads();
        int r = s_base + x - c;
        for (int w = 0; w < warp; w++) r += s_wsum[w];
#pragma unroll
        for (int j = 0; j < 16; j++) {
            if (v[j] > 0) { if (r < NMAX) s_pos[r] = base + j; r++; }
        }
        __syncthreads();
        if (tid == 0) {
            int tot = s_base;
            for (int w = 0; w < 4; w++) tot += s_wsum[w];
            s_base = tot;
        }
        __syncthreads();
    }
    const int cnt  = (s_base < NMAX) ? s_base : NMAX;
    const int last = cnt - 1;

    if (tid < HT) swr[tid] = Wr[h0 + tid];

    // ---- preload Wk slice as f32x2 pairs: 64 regs / thread ----
    unsigned long long wk2[HT / 2];
#pragma unroll
    for (int j = 0; j < HT / 2; j++) {
        float w0 = Wk[(size_t)(h0 + 2 * j) * DD + tid];
        float w1 = Wk[(size_t)(h0 + 2 * j + 1) * DD + tid];
        asm("mov.b64 %0,{%1,%2};" : "=l"(wk2[j]) : "f"(w0), "f"(w1));
    }

    // ---- preload ALL sentence-row slices into smem (one MLP burst) ----
    {
        int tot4 = cnt * (HT / 4);
        float4* sh4 = (float4*)sh;
        for (int i = tid; i < tot4; i += TPB) {
            int row = i >> 4;            // HT/4 = 16
            int c4  = i & 15;
            sh4[i] = *(const float4*)(hid + ((size_t)b * SS + s_pos[row]) * HH
                                          + h0 + c4 * 4);
        }
    }
    __syncthreads();

    // ---- mainloop: pure vector LDS + FFMA2, exclusive partial stores ----
    for (int n = 0; n < cnt; n++) {
        const ulonglong2* srow = (const ulonglong2*)&sh[n * HT];
        unsigned long long a0 = 0ull, a1 = 0ull;   // {0.f,0.f}
#pragma unroll
        for (int j = 0; j < HT / 4; j++) {
            ulonglong2 s4 = srow[j];
            asm("fma.rn.f32x2 %0,%1,%2,%0;" : "+l"(a0) : "l"(s4.x), "l"(wk2[2 * j]));
            asm("fma.rn.f32x2 %0,%1,%2,%0;" : "+l"(a1) : "l"(s4.y), "l"(wk2[2 * j + 1]));
        }
        float lo0, hi0, lo1, hi1;
        asm("mov.b64 {%0,%1},%2;" : "=f"(lo0), "=f"(hi0) : "l"(a0));
        asm("mov.b64 {%0,%1},%2;" : "=f"(lo1), "=f"(hi1) : "l"(a1));
        g_Kp[b][tile][n][tid] = (lo0 + hi0) + (lo1 + hi1);

        if (tid < HT) {                 // V partial: 2 warps, 1 store each
            float vp = sh[n * HT + tid] * swr[tid];
#pragma unroll
            for (int off = 16; off; off >>= 1)
                vp += __shfl_down_sync(0xffffffffu, vp, off);
            if (lane == 0) g_Vp[b][n][tile * 2 + warp] = vp;
        }
    }

    // ---- Q: only the last sentence row ----
    {
        const float* srow = &sh[last * HT];
        float aq0 = 0.0f, aq1 = 0.0f;
#pragma unroll
        for (int j = 0; j < HT; j += 2) {
            aq0 += srow[j]     * Wq[(size_t)(h0 + j) * DD + tid];
            aq1 += srow[j + 1] * Wq[(size_t)(h0 + j + 1) * DD + tid];
        }
        g_Qp[b][tile][tid] = aq0 + aq1;
    }
}

// ---------------------------------------------------------------------------
// Kernel 2: reduce partials. Blocks [0,512): K. Blocks [512,520): Q+V per b.
// ---------------------------------------------------------------------------
__global__ void __launch_bounds__(TPB)
k_reduce() {
    const int blk = blockIdx.x, tid = threadIdx.x;
    if (blk < 512) {
        int item = blk * TPB + tid;          // b*8192 + n*128 + d
        int b = item >> 13, rem = item & 8191;
        const float* p = &g_Kp[b][0][0][0] + rem;
        float s = 0.0f;
#pragma unroll
        for (int t = 0; t < NT; t++) s += p[(size_t)t * NMAX * DD];
        (&g_K[0][0][0])[item] = s;
    } else {
        int b = blk - 512;
        float s = 0.0f;
#pragma unroll
        for (int t = 0; t < NT; t++) s += g_Qp[b][t][tid];
        g_Q[b][tid] = s;
        if (tid < NMAX) {
            float v = 0.0f;
#pragma unroll
            for (int s2 = 0; s2 < NT * 2; s2++) v += g_Vp[b][tid][s2];
            g_V[b][tid] = v;
        }
    }
}

// ---------------------------------------------------------------------------
// Kernel 3: fused RoPE + logits + softmax + reward + pairwise loss.
// grid=1, 1024 threads (128 per batch).
// ---------------------------------------------------------------------------
__global__ void __launch_bounds__(1024)
k_attn_loss(const int*   __restrict__ mask,
            const float* __restrict__ bq,
            const float* __restrict__ bk,
            const float* __restrict__ br,
            float* __restrict__ out, int out_size) {
    const int tid = threadIdx.x;
    const int b = tid >> 7, t = tid & 127, lane = tid & 31, w4 = (tid >> 5) & 3;

    __shared__ float qs[BB][DD];
    __shared__ float lg[BB][NMAX];
    __shared__ int   s_part[BB][4];
    __shared__ float s_rew[BB];

    // count sentences for this batch
    int c = 0;
    const int* mrow = mask + b * SS;
    for (int j = t; j < SS; j += 128) c += (mrow[j] > 0);
#pragma unroll
    for (int off = 16; off; off >>= 1) c += __shfl_down_sync(0xffffffffu, c, off);
    if (lane == 0) s_part[b][w4] = c;
    __syncthreads();
    int cnt = s_part[b][0] + s_part[b][1] + s_part[b][2] + s_part[b][3];
    cnt = (cnt < NMAX) ? cnt : NMAX;
    const int last = cnt - 1;

    const float LN_THETA = 9.210340371976184f;   // ln(10000)

    // RoPE the single q row at rank = last
    {
        float freq = expf(-LN_THETA * (float)(2 * (t >> 1)) / 128.0f);
        float qv = g_Q[b][t] + bq[t];
        float a = (float)last * freq;
        float cq = cosf(a), sq = sinf(a);
        float qp = __shfl_xor_sync(0xffffffffu, qv, 1);
        qs[b][t] = ((t & 1) == 0) ? (qv * cq - qp * sq) : (qp * sq + qv * cq);
    }
    __syncthreads();

    // logits: warp w4 handles n = w4, w4+4, ...
    for (int n = w4; n < cnt; n += 4) {
        float dot = 0.0f;
#pragma unroll
        for (int s4 = 0; s4 < 4; s4++) {
            int d = lane + s4 * 32;
            float kv = g_K[b][n][d] + bk[d];
            float f = expf(-LN_THETA * (float)(2 * (d >> 1)) / 128.0f);
            float a = (float)n * f;
            float cn = cosf(a), sn = sinf(a);
            float kp = __shfl_xor_sync(0xffffffffu, kv, 1);
            float kr = ((d & 1) == 0) ? (kv * cn - kp * sn) : (kp * sn + kv * cn);
            dot += qs[b][d] * kr;
        }
#pragma unroll
        for (int off = 16; off; off >>= 1)
            dot += __shfl_xor_sync(0xffffffffu, dot, off);
        if (lane == 0) lg[b][n] = dot * 0.08838834764831845f;  // 1/sqrt(128)
    }
    __syncthreads();

    if (t == 0) {
        float mx = -3.0e38f;
        for (int n = 0; n < cnt; n++) mx = fmaxf(mx, lg[b][n]);
        float sum = 0.0f, rew = 0.0f, prev = 0.0f;
        for (int n = 0; n < cnt; n++) {
            float e = expf(lg[b][n] - mx);
            float v = g_V[b][n] + br[0];
            rew += e * (v - prev);        // sr[n] = v[n] - v[n-1]
            sum += e;
            prev = v;
        }
        s_rew[b] = rew / sum;
    }
    __syncthreads();

    if (tid == 0) {
        float loss = 0.0f;
#pragma unroll
        for (int i = 0; i < 4; i++) {
            float x = s_rew[i] - s_rew[i + 4];
            loss += (x >= 0.0f) ? log1pf(expf(-x)) : (-x + log1pf(expf(x)));
        }
        loss *= 0.25f;
        if (out_size >= 9) {
            out[0] = loss;
            for (int i = 0; i < 8; i++) out[1 + i] = s_rew[i];
        } else if (out_size == 8) {
            for (int i = 0; i < 8; i++) out[i] = s_rew[i];
        } else {
            out[0] = loss;
        }
    }
}

// ---------------------------------------------------------------------------
extern "C" void kernel_launch(void* const* d_in, const int* in_sizes, int n_in,
                              void* d_out, int out_size) {
    const float* hid  = (const float*)d_in[0];
    const int*   mask = (const int*)  d_in[1];
    const float* Wq   = (const float*)d_in[2];
    const float* bq   = (const float*)d_in[3];
    const float* Wk   = (const float*)d_in[4];
    const float* bk   = (const float*)d_in[5];
    const float* Wr   = (const float*)d_in[6];
    const float* br   = (const float*)d_in[7];
    float* out = (float*)d_out;

    k_proj<<<dim3(NT, BB), TPB>>>(hid, mask, Wq, Wk, Wr);
    k_reduce<<<512 + BB, TPB>>>();
    k_attn_loss<<<1, 1024>>>(mask, bq, bk, br, out, out_size);
}

// round 4
// speedup vs baseline: 1.1076x; 1.0383x over previous
#include <cuda_runtime.h>
#include <math.h>

#define BB 8
#define SS 4096
#define HH 4096
#define DD 128
#define NMAX 64
#define NT 64
#define HT 64            /* HH / NT */
#define TPB 128
#define SPL 2            /* row split */

// -------- persistent scratch: zero at module load; k_attn_loss re-zeros ----
__device__ float g_K[BB][NMAX][DD];   // 256 KB
__device__ float g_Q[BB][DD];
__device__ float g_V[BB][NMAX];

__device__ __forceinline__ void red_v2(float* p, float x, float y) {
    asm volatile("red.global.add.v2.f32 [%0], {%1,%2};"
                 :: "l"(p), "f"(x), "f"(y) : "memory");
}

// ---------------------------------------------------------------------------
// Kernel 1: projections at sentence rows. grid=(NT, B, SPL), 128 threads.
// Block (tile,b,s) handles rows n = s, s+2, ... for h-slice [h0,h0+64).
// Results RED-accumulated into g_K/g_Q/g_V (attn kernel re-zeros them).
// ---------------------------------------------------------------------------
__global__ void __launch_bounds__(TPB)
k_proj(const float* __restrict__ hid,
       const int*   __restrict__ mask,
       const float* __restrict__ Wq,
       const float* __restrict__ Wk,
       const float* __restrict__ Wr) {
    const int b     = blockIdx.y;
    const int tile  = blockIdx.x;
    const int split = blockIdx.z;
    const int h0    = tile * HT;
    const int tid   = threadIdx.x;
    const int lane  = tid & 31, warp = tid >> 5;

    __shared__ __align__(16) float sh[(NMAX / 2) * HT];   // 8 KB row tile
    __shared__ __align__(16) float sK[NMAX / 2][DD];      // 16 KB K staging
    __shared__ float swr[HT];
    __shared__ int   s_pos[NMAX];
    __shared__ int   s_wsum[4];
    __shared__ int   s_base;

    // ---- issue Wk register preload FIRST (overlaps the scan below) ----
    unsigned long long wk2[HT / 2];
#pragma unroll
    for (int j = 0; j < HT / 2; j++) {
        float w0 = Wk[(size_t)(h0 + 2 * j) * DD + tid];
        float w1 = Wk[(size_t)(h0 + 2 * j + 1) * DD + tid];
        asm("mov.b64 %0,{%1,%2};" : "=l"(wk2[j]) : "f"(w0), "f"(w1));
    }
    if (tid < HT) swr[tid] = Wr[h0 + tid];

    // ---- inline mask scan: 2 passes, int4 loads ----
    if (tid == 0) s_base = 0;
    __syncthreads();
    const int* mrow = mask + b * SS;
    for (int pass = 0; pass < 2; pass++) {
        int base = pass * (SS / 2) + tid * 16;
        const int4* m4 = (const int4*)(mrow + base);
        int v[16];
        { int4 t0 = m4[0], t1 = m4[1], t2 = m4[2], t3 = m4[3];
          v[0]=t0.x; v[1]=t0.y; v[2]=t0.z; v[3]=t0.w;
          v[4]=t1.x; v[5]=t1.y; v[6]=t1.z; v[7]=t1.w;
          v[8]=t2.x; v[9]=t2.y; v[10]=t2.z; v[11]=t2.w;
          v[12]=t3.x; v[13]=t3.y; v[14]=t3.z; v[15]=t3.w; }
        int c = 0;
#pragma unroll
        for (int j = 0; j < 16; j++) c += (v[j] > 0);
        int x = c;
#pragma unroll
        for (int off = 1; off < 32; off <<= 1) {
            int y = __shfl_up_sync(0xffffffffu, x, off);
            if (lane >= off) x += y;
        }
        if (lane == 31) s_wsum[warp] = x;
        __syncthreads();
        int r = s_base + x - c;
        for (int w = 0; w < warp; w++) r += s_wsum[w];
#pragma unroll
        for (int j = 0; j < 16; j++) {
            if (v[j] > 0) { if (r < NMAX) s_pos[r] = base + j; r++; }
        }
        __syncthreads();
        if (tid == 0) {
            int tot = s_base;
            for (int w = 0; w < 4; w++) tot += s_wsum[w];
            s_base = tot;
        }
        __syncthreads();
    }
    const int cnt  = (s_base < NMAX) ? s_base : NMAX;
    const int nloc = (cnt > split) ? ((cnt - split + 1) >> 1) : 0;

    // ---- preload this block's sentence-row slices into smem ----
    {
        int tot4 = nloc * (HT / 4);
        float4* sh4 = (float4*)sh;
        for (int i = tid; i < tot4; i += TPB) {
            int row = i >> 4;            // HT/4 = 16
            int c4  = i & 15;
            sh4[i] = *(const float4*)(hid +
                ((size_t)b * SS + s_pos[split + 2 * row]) * HH + h0 + c4 * 4);
        }
    }
    __syncthreads();

    // ---- mainloop: 2 rows per iteration, 4 independent FFMA2 chains ----
    int i = 0;
    for (; i + 2 <= nloc; i += 2) {
        const ulonglong2* r0 = (const ulonglong2*)&sh[i * HT];
        const ulonglong2* r1 = (const ulonglong2*)&sh[(i + 1) * HT];
        unsigned long long a00 = 0ull, a01 = 0ull, a10 = 0ull, a11 = 0ull;
#pragma unroll
        for (int j = 0; j < HT / 4; j++) {
            ulonglong2 x0 = r0[j], x1 = r1[j];
            asm("fma.rn.f32x2 %0,%1,%2,%0;" : "+l"(a00) : "l"(x0.x), "l"(wk2[2*j]));
            asm("fma.rn.f32x2 %0,%1,%2,%0;" : "+l"(a10) : "l"(x1.x), "l"(wk2[2*j]));
            asm("fma.rn.f32x2 %0,%1,%2,%0;" : "+l"(a01) : "l"(x0.y), "l"(wk2[2*j+1]));
            asm("fma.rn.f32x2 %0,%1,%2,%0;" : "+l"(a11) : "l"(x1.y), "l"(wk2[2*j+1]));
        }
        float l0,h0f,l1,h1f,l2,h2f,l3,h3f;
        asm("mov.b64 {%0,%1},%2;" : "=f"(l0), "=f"(h0f) : "l"(a00));
        asm("mov.b64 {%0,%1},%2;" : "=f"(l1), "=f"(h1f) : "l"(a01));
        asm("mov.b64 {%0,%1},%2;" : "=f"(l2), "=f"(h2f) : "l"(a10));
        asm("mov.b64 {%0,%1},%2;" : "=f"(l3), "=f"(h3f) : "l"(a11));
        sK[i][tid]     = (l0 + h0f) + (l1 + h1f);
        sK[i + 1][tid] = (l2 + h2f) + (l3 + h3f);

        if (tid < HT) {   // V partials for both rows (warps 0,1)
            float vp0 = sh[i * HT + tid] * swr[tid];
            float vp1 = sh[(i + 1) * HT + tid] * swr[tid];
#pragma unroll
            for (int off = 16; off; off >>= 1) {
                vp0 += __shfl_down_sync(0xffffffffu, vp0, off);
                vp1 += __shfl_down_sync(0xffffffffu, vp1, off);
            }
            if (lane == 0) {
                atomicAdd(&g_V[b][split + 2 * i], vp0);
                atomicAdd(&g_V[b][split + 2 * (i + 1)], vp1);
            }
        }
    }
    if (i < nloc) {       // odd tail row
        const ulonglong2* r0 = (const ulonglong2*)&sh[i * HT];
        unsigned long long a00 = 0ull, a01 = 0ull;
#pragma unroll
        for (int j = 0; j < HT / 4; j++) {
            ulonglong2 x0 = r0[j];
            asm("fma.rn.f32x2 %0,%1,%2,%0;" : "+l"(a00) : "l"(x0.x), "l"(wk2[2*j]));
            asm("fma.rn.f32x2 %0,%1,%2,%0;" : "+l"(a01) : "l"(x0.y), "l"(wk2[2*j+1]));
        }
        float l0,h0f,l1,h1f;
        asm("mov.b64 {%0,%1},%2;" : "=f"(l0), "=f"(h0f) : "l"(a00));
        asm("mov.b64 {%0,%1},%2;" : "=f"(l1), "=f"(h1f) : "l"(a01));
        sK[i][tid] = (l0 + h0f) + (l1 + h1f);
        if (tid < HT) {
            float vp0 = sh[i * HT + tid] * swr[tid];
#pragma unroll
            for (int off = 16; off; off >>= 1)
                vp0 += __shfl_down_sync(0xffffffffu, vp0, off);
            if (lane == 0) atomicAdd(&g_V[b][split + 2 * i], vp0);
        }
    }

    // ---- Q: only the owner of the last sentence row ----
    if (((cnt - 1) & 1) == split) {
        int il = (cnt - 1 - split) >> 1;
        const float* srow = &sh[il * HT];
        float aq0 = 0.0f, aq1 = 0.0f;
#pragma unroll
        for (int j = 0; j < HT; j += 2) {
            aq0 += srow[j]     * Wq[(size_t)(h0 + j) * DD + tid];
            aq1 += srow[j + 1] * Wq[(size_t)(h0 + j + 1) * DD + tid];
        }
        atomicAdd(&g_Q[b][tid], aq0 + aq1);
    }
    __syncthreads();

    // ---- flush staged K rows with vector REDs ----
    for (int j = tid; j < nloc * (DD / 2); j += TPB) {
        int row = j >> 6, dh = j & 63;
        float2 v = *(const float2*)&sK[row][2 * dh];
        red_v2(&g_K[b][split + 2 * row][2 * dh], v.x, v.y);
    }
}

// ---------------------------------------------------------------------------
// Kernel 2: fused RoPE + logits + softmax + reward + pairwise loss,
// then re-zero the accumulators for the next graph replay.
// grid=1, 1024 threads (128 per batch).
// ---------------------------------------------------------------------------
__global__ void __launch_bounds__(1024)
k_attn_loss(const int*   __restrict__ mask,
            const float* __restrict__ bq,
            const float* __restrict__ bk,
            const float* __restrict__ br,
            float* __restrict__ out, int out_size) {
    const int tid = threadIdx.x;
    const int b = tid >> 7, t = tid & 127, lane = tid & 31, w4 = (tid >> 5) & 3;

    __shared__ float qs[BB][DD];
    __shared__ float lg[BB][NMAX];
    __shared__ int   s_part[BB][4];
    __shared__ float s_rew[BB];

    // count sentences for this batch
    int c = 0;
    const int* mrow = mask + b * SS;
    for (int j = t; j < SS; j += 128) c += (mrow[j] > 0);
#pragma unroll
    for (int off = 16; off; off >>= 1) c += __shfl_down_sync(0xffffffffu, c, off);
    if (lane == 0) s_part[b][w4] = c;
    __syncthreads();
    int cnt = s_part[b][0] + s_part[b][1] + s_part[b][2] + s_part[b][3];
    cnt = (cnt < NMAX) ? cnt : NMAX;
    const int last = cnt - 1;

    const float LN_THETA = 9.210340371976184f;   // ln(10000)

    // RoPE the single q row at rank = last
    {
        float freq = expf(-LN_THETA * (float)(2 * (t >> 1)) / 128.0f);
        float qv = g_Q[b][t] + bq[t];
        float a = (float)last * freq;
        float cq = cosf(a), sq = sinf(a);
        float qp = __shfl_xor_sync(0xffffffffu, qv, 1);
        qs[b][t] = ((t & 1) == 0) ? (qv * cq - qp * sq) : (qp * sq + qv * cq);
    }
    __syncthreads();

    // logits: warp w4 handles n = w4, w4+4, ...
    for (int n = w4; n < cnt; n += 4) {
        float dot = 0.0f;
#pragma unroll
        for (int s4 = 0; s4 < 4; s4++) {
            int d = lane + s4 * 32;
            float kv = g_K[b][n][d] + bk[d];
            float f = expf(-LN_THETA * (float)(2 * (d >> 1)) / 128.0f);
            float a = (float)n * f;
            float cn = cosf(a), sn = sinf(a);
            float kp = __shfl_xor_sync(0xffffffffu, kv, 1);
            float kr = ((d & 1) == 0) ? (kv * cn - kp * sn) : (kp * sn + kv * cn);
            dot += qs[b][d] * kr;
        }
#pragma unroll
        for (int off = 16; off; off >>= 1)
            dot += __shfl_xor_sync(0xffffffffu, dot, off);
        if (lane == 0) lg[b][n] = dot * 0.08838834764831845f;  // 1/sqrt(128)
    }
    __syncthreads();

    if (t == 0) {
        float mx = -3.0e38f;
        for (int n = 0; n < cnt; n++) mx = fmaxf(mx, lg[b][n]);
        float sum = 0.0f, rew = 0.0f, prev = 0.0f;
        for (int n = 0; n < cnt; n++) {
            float e = expf(lg[b][n] - mx);
            float v = g_V[b][n] + br[0];
            rew += e * (v - prev);        // sr[n] = v[n] - v[n-1]
            sum += e;
            prev = v;
        }
        s_rew[b] = rew / sum;
    }
    __syncthreads();

    if (tid == 0) {
        float loss = 0.0f;
#pragma unroll
        for (int i = 0; i < 4; i++) {
            float x = s_rew[i] - s_rew[i + 4];
            loss += (x >= 0.0f) ? log1pf(expf(-x)) : (-x + log1pf(expf(x)));
        }
        loss *= 0.25f;
        if (out_size >= 9) {
            out[0] = loss;
            for (int i = 0; i < 8; i++) out[1 + i] = s_rew[i];
        } else if (out_size == 8) {
            for (int i = 0; i < 8; i++) out[i] = s_rew[i];
        } else {
            out[0] = loss;
        }
    }

    // ---- re-zero accumulators for the next replay (all reads are done) ----
    float4 z4 = make_float4(0.f, 0.f, 0.f, 0.f);
    float4* kz = (float4*)&g_K[0][0][0];
    for (int j = tid; j < BB * NMAX * DD / 4; j += 1024) kz[j] = z4;
    (&g_Q[0][0])[tid] = 0.0f;                 // BB*DD == 1024 exactly
    if (tid < BB * NMAX) (&g_V[0][0])[tid] = 0.0f;
}

// ---------------------------------------------------------------------------
extern "C" void kernel_launch(void* const* d_in, const int* in_sizes, int n_in,
                              void* d_out, int out_size) {
    const float* hid  = (const float*)d_in[0];
    const int*   mask = (const int*)  d_in[1];
    const float* Wq   = (const float*)d_in[2];
    const float* bq   = (const float*)d_in[3];
    const float* Wk   = (const float*)d_in[4];
    const float* bk   = (const float*)d_in[5];
    const float* Wr   = (const float*)d_in[6];
    const float* br   = (const float*)d_in[7];
    float* out = (float*)d_out;

    k_proj<<<dim3(NT, BB, SPL), TPB>>>(hid, mask, Wq, Wk, Wr);
    k_attn_loss<<<1, 1024>>>(mask, bq, bk, br, out, out_size);
}

// round 5
// speedup vs baseline: 1.3596x; 1.2275x over previous
#include <cuda_runtime.h>
#include <math.h>

#define BB 8
#define SS 4096
#define HH 4096
#define DD 128
#define NMAX 64
#define NT 64
#define HT 64            /* HH / NT */
#define TPB 128
#define SPL 2            /* row split */

// -------- persistent scratch: zero at module load; k_attn_loss re-zeros ----
__device__ float g_K[BB][NMAX][DD];   // 256 KB
__device__ float g_Q[BB][DD];
__device__ float g_V[BB][NMAX];

__device__ __forceinline__ void red_v2(float* p, float x, float y) {
    asm volatile("red.global.add.v2.f32 [%0], {%1,%2};"
                 :: "l"(p), "f"(x), "f"(y) : "memory");
}

// ---------------------------------------------------------------------------
// Kernel 1: projections at sentence rows. grid=(NT, B, SPL), 128 threads.
// Block (tile,b,s) handles rows n = s, s+2, ... for h-slice [h0,h0+64).
// Results RED-accumulated into g_K/g_Q/g_V (attn kernel re-zeros them).
// ---------------------------------------------------------------------------
__global__ void __launch_bounds__(TPB)
k_proj(const float* __restrict__ hid,
       const int*   __restrict__ mask,
       const float* __restrict__ Wq,
       const float* __restrict__ Wk,
       const float* __restrict__ Wr) {
    const int b     = blockIdx.y;
    const int tile  = blockIdx.x;
    const int split = blockIdx.z;
    const int h0    = tile * HT;
    const int tid   = threadIdx.x;
    const int lane  = tid & 31, warp = tid >> 5;

    __shared__ __align__(16) float sh[(NMAX / 2) * HT];   // 8 KB row tile
    __shared__ __align__(16) float sK[NMAX / 2][DD];      // 16 KB K staging
    __shared__ float swr[HT];
    __shared__ int   s_pos[NMAX];
    __shared__ int   s_wsum[4];
    __shared__ int   s_base;

    // ---- issue Wk register preload FIRST (overlaps the scan below) ----
    unsigned long long wk2[HT / 2];
#pragma unroll
    for (int j = 0; j < HT / 2; j++) {
        float w0 = Wk[(size_t)(h0 + 2 * j) * DD + tid];
        float w1 = Wk[(size_t)(h0 + 2 * j + 1) * DD + tid];
        asm("mov.b64 %0,{%1,%2};" : "=l"(wk2[j]) : "f"(w0), "f"(w1));
    }
    if (tid < HT) swr[tid] = Wr[h0 + tid];

    // ---- inline mask scan: 2 passes, int4 loads ----
    if (tid == 0) s_base = 0;
    __syncthreads();
    const int* mrow = mask + b * SS;
    for (int pass = 0; pass < 2; pass++) {
        int base = pass * (SS / 2) + tid * 16;
        const int4* m4 = (const int4*)(mrow + base);
        int v[16];
        { int4 t0 = m4[0], t1 = m4[1], t2 = m4[2], t3 = m4[3];
          v[0]=t0.x; v[1]=t0.y; v[2]=t0.z; v[3]=t0.w;
          v[4]=t1.x; v[5]=t1.y; v[6]=t1.z; v[7]=t1.w;
          v[8]=t2.x; v[9]=t2.y; v[10]=t2.z; v[11]=t2.w;
          v[12]=t3.x; v[13]=t3.y; v[14]=t3.z; v[15]=t3.w; }
        int c = 0;
#pragma unroll
        for (int j = 0; j < 16; j++) c += (v[j] > 0);
        int x = c;
#pragma unroll
        for (int off = 1; off < 32; off <<= 1) {
            int y = __shfl_up_sync(0xffffffffu, x, off);
            if (lane >= off) x += y;
        }
        if (lane == 31) s_wsum[warp] = x;
        __syncthreads();
        int r = s_base + x - c;
        for (int w = 0; w < warp; w++) r += s_wsum[w];
#pragma unroll
        for (int j = 0; j < 16; j++) {
            if (v[j] > 0) { if (r < NMAX) s_pos[r] = base + j; r++; }
        }
        __syncthreads();
        if (tid == 0) {
            int tot = s_base;
            for (int w = 0; w < 4; w++) tot += s_wsum[w];
            s_base = tot;
        }
        __syncthreads();
    }
    const int cnt  = (s_base < NMAX) ? s_base : NMAX;
    const int nloc = (cnt > split) ? ((cnt - split + 1) >> 1) : 0;

    // ---- preload this block's sentence-row slices into smem ----
    {
        int tot4 = nloc * (HT / 4);
        float4* sh4 = (float4*)sh;
        for (int i = tid; i < tot4; i += TPB) {
            int row = i >> 4;            // HT/4 = 16
            int c4  = i & 15;
            sh4[i] = *(const float4*)(hid +
                ((size_t)b * SS + s_pos[split + 2 * row]) * HH + h0 + c4 * 4);
        }
    }
    __syncthreads();

    // ---- mainloop: 2 rows per iteration, 4 independent FFMA2 chains ----
    int i = 0;
    for (; i + 2 <= nloc; i += 2) {
        const ulonglong2* r0 = (const ulonglong2*)&sh[i * HT];
        const ulonglong2* r1 = (const ulonglong2*)&sh[(i + 1) * HT];
        unsigned long long a00 = 0ull, a01 = 0ull, a10 = 0ull, a11 = 0ull;
#pragma unroll
        for (int j = 0; j < HT / 4; j++) {
            ulonglong2 x0 = r0[j], x1 = r1[j];
            asm("fma.rn.f32x2 %0,%1,%2,%0;" : "+l"(a00) : "l"(x0.x), "l"(wk2[2*j]));
            asm("fma.rn.f32x2 %0,%1,%2,%0;" : "+l"(a10) : "l"(x1.x), "l"(wk2[2*j]));
            asm("fma.rn.f32x2 %0,%1,%2,%0;" : "+l"(a01) : "l"(x0.y), "l"(wk2[2*j+1]));
            asm("fma.rn.f32x2 %0,%1,%2,%0;" : "+l"(a11) : "l"(x1.y), "l"(wk2[2*j+1]));
        }
        float l0,h0f,l1,h1f,l2,h2f,l3,h3f;
        asm("mov.b64 {%0,%1},%2;" : "=f"(l0), "=f"(h0f) : "l"(a00));
        asm("mov.b64 {%0,%1},%2;" : "=f"(l1), "=f"(h1f) : "l"(a01));
        asm("mov.b64 {%0,%1},%2;" : "=f"(l2), "=f"(h2f) : "l"(a10));
        asm("mov.b64 {%0,%1},%2;" : "=f"(l3), "=f"(h3f) : "l"(a11));
        sK[i][tid]     = (l0 + h0f) + (l1 + h1f);
        sK[i + 1][tid] = (l2 + h2f) + (l3 + h3f);

        if (tid < HT) {   // V partials for both rows (warps 0,1)
            float vp0 = sh[i * HT + tid] * swr[tid];
            float vp1 = sh[(i + 1) * HT + tid] * swr[tid];
#pragma unroll
            for (int off = 16; off; off >>= 1) {
                vp0 += __shfl_down_sync(0xffffffffu, vp0, off);
                vp1 += __shfl_down_sync(0xffffffffu, vp1, off);
            }
            if (lane == 0) {
                atomicAdd(&g_V[b][split + 2 * i], vp0);
                atomicAdd(&g_V[b][split + 2 * (i + 1)], vp1);
            }
        }
    }
    if (i < nloc) {       // odd tail row
        const ulonglong2* r0 = (const ulonglong2*)&sh[i * HT];
        unsigned long long a00 = 0ull, a01 = 0ull;
#pragma unroll
        for (int j = 0; j < HT / 4; j++) {
            ulonglong2 x0 = r0[j];
            asm("fma.rn.f32x2 %0,%1,%2,%0;" : "+l"(a00) : "l"(x0.x), "l"(wk2[2*j]));
            asm("fma.rn.f32x2 %0,%1,%2,%0;" : "+l"(a01) : "l"(x0.y), "l"(wk2[2*j+1]));
        }
        float l0,h0f,l1,h1f;
        asm("mov.b64 {%0,%1},%2;" : "=f"(l0), "=f"(h0f) : "l"(a00));
        asm("mov.b64 {%0,%1},%2;" : "=f"(l1), "=f"(h1f) : "l"(a01));
        sK[i][tid] = (l0 + h0f) + (l1 + h1f);
        if (tid < HT) {
            float vp0 = sh[i * HT + tid] * swr[tid];
#pragma unroll
            for (int off = 16; off; off >>= 1)
                vp0 += __shfl_down_sync(0xffffffffu, vp0, off);
            if (lane == 0) atomicAdd(&g_V[b][split + 2 * i], vp0);
        }
    }

    // ---- Q: only the owner of the last sentence row ----
    if (((cnt - 1) & 1) == split) {
        int il = (cnt - 1 - split) >> 1;
        const float* srow = &sh[il * HT];
        float aq0 = 0.0f, aq1 = 0.0f;
#pragma unroll
        for (int j = 0; j < HT; j += 2) {
            aq0 += srow[j]     * Wq[(size_t)(h0 + j) * DD + tid];
            aq1 += srow[j + 1] * Wq[(size_t)(h0 + j + 1) * DD + tid];
        }
        atomicAdd(&g_Q[b][tid], aq0 + aq1);
    }
    __syncthreads();

    // ---- flush staged K rows with vector REDs ----
    for (int j = tid; j < nloc * (DD / 2); j += TPB) {
        int row = j >> 6, dh = j & 63;
        float2 v = *(const float2*)&sK[row][2 * dh];
        red_v2(&g_K[b][split + 2 * row][2 * dh], v.x, v.y);
    }
}

// ---------------------------------------------------------------------------
// Kernel 2: fused RoPE + logits + softmax + reward + pairwise loss,
// then re-zero the accumulators for the next graph replay.
// grid=1, 1024 threads (128 per batch). ALL trig/exp via MUFU intrinsics.
// ---------------------------------------------------------------------------
__global__ void __launch_bounds__(1024)
k_attn_loss(const int*   __restrict__ mask,
            const float* __restrict__ bq,
            const float* __restrict__ bk,
            const float* __restrict__ br,
            float* __restrict__ out, int out_size) {
    const int tid = threadIdx.x;
    const int b = tid >> 7, t = tid & 127, lane = tid & 31, w4 = (tid >> 5) & 3;

    __shared__ float qs[BB][DD];
    __shared__ float lg[BB][NMAX];
    __shared__ int   s_part[BB][4];
    __shared__ float s_rew[BB];

    // count sentences for this batch
    int c = 0;
    const int* mrow = mask + b * SS;
    for (int j = t; j < SS; j += 128) c += (mrow[j] > 0);
#pragma unroll
    for (int off = 16; off; off >>= 1) c += __shfl_down_sync(0xffffffffu, c, off);
    if (lane == 0) s_part[b][w4] = c;
    __syncthreads();
    int cnt = s_part[b][0] + s_part[b][1] + s_part[b][2] + s_part[b][3];
    cnt = (cnt < NMAX) ? cnt : NMAX;
    const int last = cnt - 1;

    const float LN_THETA = 9.210340371976184f;   // ln(10000)

    // RoPE the single q row at rank = last (MUFU trig)
    {
        float freq = __expf(-LN_THETA * (float)(2 * (t >> 1)) * (1.0f / 128.0f));
        float qv = g_Q[b][t] + bq[t];
        float a = (float)last * freq;
        float cq = __cosf(a), sq = __sinf(a);
        float qp = __shfl_xor_sync(0xffffffffu, qv, 1);
        qs[b][t] = ((t & 1) == 0) ? (qv * cq - qp * sq) : (qp * sq + qv * cq);
    }
    __syncthreads();

    // hoist d-dependent freqs out of the n loop
    float fr[4];
#pragma unroll
    for (int s4 = 0; s4 < 4; s4++) {
        int d = lane + s4 * 32;
        fr[s4] = __expf(-LN_THETA * (float)(2 * (d >> 1)) * (1.0f / 128.0f));
    }

    // logits: warp w4 handles n = w4, w4+4, ... (MUFU trig)
    for (int n = w4; n < cnt; n += 4) {
        float dot = 0.0f;
        float nf = (float)n;
#pragma unroll
        for (int s4 = 0; s4 < 4; s4++) {
            int d = lane + s4 * 32;
            float kv = g_K[b][n][d] + bk[d];
            float a = nf * fr[s4];
            float cn = __cosf(a), sn = __sinf(a);
            float kp = __shfl_xor_sync(0xffffffffu, kv, 1);
            float kr = ((d & 1) == 0) ? (kv * cn - kp * sn) : (kp * sn + kv * cn);
            dot += qs[b][d] * kr;
        }
#pragma unroll
        for (int off = 16; off; off >>= 1)
            dot += __shfl_xor_sync(0xffffffffu, dot, off);
        if (lane == 0) lg[b][n] = dot * 0.08838834764831845f;  // 1/sqrt(128)
    }
    __syncthreads();

    if (t == 0) {
        float mx = -3.0e38f;
        for (int n = 0; n < cnt; n++) mx = fmaxf(mx, lg[b][n]);
        float sum = 0.0f, rew = 0.0f, prev = 0.0f;
        for (int n = 0; n < cnt; n++) {
            float e = __expf(lg[b][n] - mx);
            float v = g_V[b][n] + br[0];
            rew += e * (v - prev);        // sr[n] = v[n] - v[n-1]
            sum += e;
            prev = v;
        }
        s_rew[b] = rew / sum;
    }
    __syncthreads();

    if (tid == 0) {
        float loss = 0.0f;
#pragma unroll
        for (int i = 0; i < 4; i++) {
            float x = s_rew[i] - s_rew[i + 4];
            loss += (x >= 0.0f) ? log1pf(expf(-x)) : (-x + log1pf(expf(x)));
        }
        loss *= 0.25f;
        if (out_size >= 9) {
            out[0] = loss;
            for (int i = 0; i < 8; i++) out[1 + i] = s_rew[i];
        } else if (out_size == 8) {
            for (int i = 0; i < 8; i++) out[i] = s_rew[i];
        } else {
            out[0] = loss;
        }
    }

    // ---- re-zero accumulators for the next replay (all reads are done) ----
    float4 z4 = make_float4(0.f, 0.f, 0.f, 0.f);
    float4* kz = (float4*)&g_K[0][0][0];
    for (int j = tid; j < BB * NMAX * DD / 4; j += 1024) kz[j] = z4;
    (&g_Q[0][0])[tid] = 0.0f;                 // BB*DD == 1024 exactly
    if (tid < BB * NMAX) (&g_V[0][0])[tid] = 0.0f;
}

// ---------------------------------------------------------------------------
extern "C" void kernel_launch(void* const* d_in, const int* in_sizes, int n_in,
                              void* d_out, int out_size) {
    const float* hid  = (const float*)d_in[0];
    const int*   mask = (const int*)  d_in[1];
    const float* Wq   = (const float*)d_in[2];
    const float* bq   = (const float*)d_in[3];
    const float* Wk   = (const float*)d_in[4];
    const float* bk   = (const float*)d_in[5];
    const float* Wr   = (const float*)d_in[6];
    const float* br   = (const float*)d_in[7];
    float* out = (float*)d_out;

    k_proj<<<dim3(NT, BB, SPL), TPB>>>(hid, mask, Wq, Wk, Wr);
    k_attn_loss<<<1, 1024>>>(mask, bq, bk, br, out, out_size);
}

// round 6
// speedup vs baseline: 1.4235x; 1.0471x over previous
#include <cuda_runtime.h>
#include <math.h>

#define BB 8
#define SS 4096
#define HH 4096
#define DD 128
#define NMAX 64
#define NT 64
#define HT 64            /* HH / NT */
#define TPB 128
#define SPL 2            /* row split */

// -------- persistent scratch: zero at module load; k_attn_loss re-zeros ----
__device__ float g_K[BB][NMAX][DD];   // 256 KB
__device__ float g_Q[BB][DD];
__device__ float g_V[BB][NMAX];

__device__ __forceinline__ void red_v2(float* p, float x, float y) {
    asm volatile("red.global.add.v2.f32 [%0], {%1,%2};"
                 :: "l"(p), "f"(x), "f"(y) : "memory");
}

// ---------------------------------------------------------------------------
// Kernel 1: projections at sentence rows. grid=(NT, B, SPL), 128 threads.
// (unchanged from R5 — measured ~16us, fma/LDS-balanced)
// ---------------------------------------------------------------------------
__global__ void __launch_bounds__(TPB)
k_proj(const float* __restrict__ hid,
       const int*   __restrict__ mask,
       const float* __restrict__ Wq,
       const float* __restrict__ Wk,
       const float* __restrict__ Wr) {
    const int b     = blockIdx.y;
    const int tile  = blockIdx.x;
    const int split = blockIdx.z;
    const int h0    = tile * HT;
    const int tid   = threadIdx.x;
    const int lane  = tid & 31, warp = tid >> 5;

    __shared__ __align__(16) float sh[(NMAX / 2) * HT];   // 8 KB row tile
    __shared__ __align__(16) float sK[NMAX / 2][DD];      // 16 KB K staging
    __shared__ float swr[HT];
    __shared__ int   s_pos[NMAX];
    __shared__ int   s_wsum[4];
    __shared__ int   s_base;

    // ---- issue Wk register preload FIRST (overlaps the scan below) ----
    unsigned long long wk2[HT / 2];
#pragma unroll
    for (int j = 0; j < HT / 2; j++) {
        float w0 = Wk[(size_t)(h0 + 2 * j) * DD + tid];
        float w1 = Wk[(size_t)(h0 + 2 * j + 1) * DD + tid];
        asm("mov.b64 %0,{%1,%2};" : "=l"(wk2[j]) : "f"(w0), "f"(w1));
    }
    if (tid < HT) swr[tid] = Wr[h0 + tid];

    // ---- inline mask scan: 2 passes, int4 loads ----
    if (tid == 0) s_base = 0;
    __syncthreads();
    const int* mrow = mask + b * SS;
    for (int pass = 0; pass < 2; pass++) {
        int base = pass * (SS / 2) + tid * 16;
        const int4* m4 = (const int4*)(mrow + base);
        int v[16];
        { int4 t0 = m4[0], t1 = m4[1], t2 = m4[2], t3 = m4[3];
          v[0]=t0.x; v[1]=t0.y; v[2]=t0.z; v[3]=t0.w;
          v[4]=t1.x; v[5]=t1.y; v[6]=t1.z; v[7]=t1.w;
          v[8]=t2.x; v[9]=t2.y; v[10]=t2.z; v[11]=t2.w;
          v[12]=t3.x; v[13]=t3.y; v[14]=t3.z; v[15]=t3.w; }
        int c = 0;
#pragma unroll
        for (int j = 0; j < 16; j++) c += (v[j] > 0);
        int x = c;
#pragma unroll
        for (int off = 1; off < 32; off <<= 1) {
            int y = __shfl_up_sync(0xffffffffu, x, off);
            if (lane >= off) x += y;
        }
        if (lane == 31) s_wsum[warp] = x;
        __syncthreads();
        int r = s_base + x - c;
        for (int w = 0; w < warp; w++) r += s_wsum[w];
#pragma unroll
        for (int j = 0; j < 16; j++) {
            if (v[j] > 0) { if (r < NMAX) s_pos[r] = base + j; r++; }
        }
        __syncthreads();
        if (tid == 0) {
            int tot = s_base;
            for (int w = 0; w < 4; w++) tot += s_wsum[w];
            s_base = tot;
        }
        __syncthreads();
    }
    const int cnt  = (s_base < NMAX) ? s_base : NMAX;
    const int nloc = (cnt > split) ? ((cnt - split + 1) >> 1) : 0;

    // ---- preload this block's sentence-row slices into smem ----
    {
        int tot4 = nloc * (HT / 4);
        float4* sh4 = (float4*)sh;
        for (int i = tid; i < tot4; i += TPB) {
            int row = i >> 4;            // HT/4 = 16
            int c4  = i & 15;
            sh4[i] = *(const float4*)(hid +
                ((size_t)b * SS + s_pos[split + 2 * row]) * HH + h0 + c4 * 4);
        }
    }
    __syncthreads();

    // ---- mainloop: 2 rows per iteration, 4 independent FFMA2 chains ----
    int i = 0;
    for (; i + 2 <= nloc; i += 2) {
        const ulonglong2* r0 = (const ulonglong2*)&sh[i * HT];
        const ulonglong2* r1 = (const ulonglong2*)&sh[(i + 1) * HT];
        unsigned long long a00 = 0ull, a01 = 0ull, a10 = 0ull, a11 = 0ull;
#pragma unroll
        for (int j = 0; j < HT / 4; j++) {
            ulonglong2 x0 = r0[j], x1 = r1[j];
            asm("fma.rn.f32x2 %0,%1,%2,%0;" : "+l"(a00) : "l"(x0.x), "l"(wk2[2*j]));
            asm("fma.rn.f32x2 %0,%1,%2,%0;" : "+l"(a10) : "l"(x1.x), "l"(wk2[2*j]));
            asm("fma.rn.f32x2 %0,%1,%2,%0;" : "+l"(a01) : "l"(x0.y), "l"(wk2[2*j+1]));
            asm("fma.rn.f32x2 %0,%1,%2,%0;" : "+l"(a11) : "l"(x1.y), "l"(wk2[2*j+1]));
        }
        float l0,h0f,l1,h1f,l2,h2f,l3,h3f;
        asm("mov.b64 {%0,%1},%2;" : "=f"(l0), "=f"(h0f) : "l"(a00));
        asm("mov.b64 {%0,%1},%2;" : "=f"(l1), "=f"(h1f) : "l"(a01));
        asm("mov.b64 {%0,%1},%2;" : "=f"(l2), "=f"(h2f) : "l"(a10));
        asm("mov.b64 {%0,%1},%2;" : "=f"(l3), "=f"(h3f) : "l"(a11));
        sK[i][tid]     = (l0 + h0f) + (l1 + h1f);
        sK[i + 1][tid] = (l2 + h2f) + (l3 + h3f);

        if (tid < HT) {   // V partials for both rows (warps 0,1)
            float vp0 = sh[i * HT + tid] * swr[tid];
            float vp1 = sh[(i + 1) * HT + tid] * swr[tid];
#pragma unroll
            for (int off = 16; off; off >>= 1) {
                vp0 += __shfl_down_sync(0xffffffffu, vp0, off);
                vp1 += __shfl_down_sync(0xffffffffu, vp1, off);
            }
            if (lane == 0) {
                atomicAdd(&g_V[b][split + 2 * i], vp0);
                atomicAdd(&g_V[b][split + 2 * (i + 1)], vp1);
            }
        }
    }
    if (i < nloc) {       // odd tail row
        const ulonglong2* r0 = (const ulonglong2*)&sh[i * HT];
        unsigned long long a00 = 0ull, a01 = 0ull;
#pragma unroll
        for (int j = 0; j < HT / 4; j++) {
            ulonglong2 x0 = r0[j];
            asm("fma.rn.f32x2 %0,%1,%2,%0;" : "+l"(a00) : "l"(x0.x), "l"(wk2[2*j]));
            asm("fma.rn.f32x2 %0,%1,%2,%0;" : "+l"(a01) : "l"(x0.y), "l"(wk2[2*j+1]));
        }
        float l0,h0f,l1,h1f;
        asm("mov.b64 {%0,%1},%2;" : "=f"(l0), "=f"(h0f) : "l"(a00));
        asm("mov.b64 {%0,%1},%2;" : "=f"(l1), "=f"(h1f) : "l"(a01));
        sK[i][tid] = (l0 + h0f) + (l1 + h1f);
        if (tid < HT) {
            float vp0 = sh[i * HT + tid] * swr[tid];
#pragma unroll
            for (int off = 16; off; off >>= 1)
                vp0 += __shfl_down_sync(0xffffffffu, vp0, off);
            if (lane == 0) atomicAdd(&g_V[b][split + 2 * i], vp0);
        }
    }

    // ---- Q: only the owner of the last sentence row ----
    if (((cnt - 1) & 1) == split) {
        int il = (cnt - 1 - split) >> 1;
        const float* srow = &sh[il * HT];
        float aq0 = 0.0f, aq1 = 0.0f;
#pragma unroll
        for (int j = 0; j < HT; j += 2) {
            aq0 += srow[j]     * Wq[(size_t)(h0 + j) * DD + tid];
            aq1 += srow[j + 1] * Wq[(size_t)(h0 + j + 1) * DD + tid];
        }
        atomicAdd(&g_Q[b][tid], aq0 + aq1);
    }
    __syncthreads();

    // ---- flush staged K rows with vector REDs ----
    for (int j = tid; j < nloc * (DD / 2); j += TPB) {
        int row = j >> 6, dh = j & 63;
        float2 v = *(const float2*)&sK[row][2 * dh];
        red_v2(&g_K[b][split + 2 * row][2 * dh], v.x, v.y);
    }
}

// ---------------------------------------------------------------------------
// Kernel 2: fused RoPE + logits + softmax + reward + pairwise loss.
// grid=1, 1024 threads (128 per batch). NO serial per-thread loops:
// softmax/reward is warp-parallel via shfl reductions.
// ---------------------------------------------------------------------------
__global__ void __launch_bounds__(1024)
k_attn_loss(const int*   __restrict__ mask,
            const float* __restrict__ bq,
            const float* __restrict__ bk,
            const float* __restrict__ br,
            float* __restrict__ out, int out_size) {
    const int tid = threadIdx.x;
    const int b = tid >> 7, t = tid & 127, lane = tid & 31, w4 = (tid >> 5) & 3;

    __shared__ float qs[BB][DD];
    __shared__ float lg[BB][NMAX];
    __shared__ int   s_part[BB][4];
    __shared__ float s_rew[BB];

    // ---- count sentences: int4 mask loads (8 LDG.128 per thread) ----
    int c = 0;
    const int4* m4 = (const int4*)(mask + b * SS);
#pragma unroll
    for (int j = 0; j < SS / 4 / 128; j++) {        // 8 iterations
        int4 m = m4[t + j * 128];
        c += (m.x > 0) + (m.y > 0) + (m.z > 0) + (m.w > 0);
    }
#pragma unroll
    for (int off = 16; off; off >>= 1) c += __shfl_down_sync(0xffffffffu, c, off);
    if (lane == 0) s_part[b][w4] = c;
    __syncthreads();
    int cnt = s_part[b][0] + s_part[b][1] + s_part[b][2] + s_part[b][3];
    cnt = (cnt < NMAX) ? cnt : NMAX;
    const int last = cnt - 1;

    const float LN_THETA = 9.210340371976184f;   // ln(10000)

    // ---- RoPE the single q row at rank = last (MUFU trig) ----
    {
        float freq = __expf(-LN_THETA * (float)(2 * (t >> 1)) * (1.0f / 128.0f));
        float qv = g_Q[b][t] + bq[t];
        float a = (float)last * freq;
        float cq = __cosf(a), sq = __sinf(a);
        float qp = __shfl_xor_sync(0xffffffffu, qv, 1);
        qs[b][t] = ((t & 1) == 0) ? (qv * cq - qp * sq) : (qp * sq + qv * cq);
    }
    __syncthreads();

    // ---- logits: warp w4 handles n = w4, w4+4, ... (MUFU trig) ----
    float fr[4];
#pragma unroll
    for (int s4 = 0; s4 < 4; s4++) {
        int d = lane + s4 * 32;
        fr[s4] = __expf(-LN_THETA * (float)(2 * (d >> 1)) * (1.0f / 128.0f));
    }
    for (int n = w4; n < cnt; n += 4) {
        float dot = 0.0f;
        float nf = (float)n;
#pragma unroll
        for (int s4 = 0; s4 < 4; s4++) {
            int d = lane + s4 * 32;
            float kv = g_K[b][n][d] + bk[d];
            float a = nf * fr[s4];
            float cn = __cosf(a), sn = __sinf(a);
            float kp = __shfl_xor_sync(0xffffffffu, kv, 1);
            float kr = ((d & 1) == 0) ? (kv * cn - kp * sn) : (kp * sn + kv * cn);
            dot += qs[b][d] * kr;
        }
#pragma unroll
        for (int off = 16; off; off >>= 1)
            dot += __shfl_xor_sync(0xffffffffu, dot, off);
        if (lane == 0) lg[b][n] = dot * 0.08838834764831845f;  // 1/sqrt(128)
    }
    __syncthreads();

    // ---- warp-parallel softmax + reward: warp 0 of each batch ----
    if (w4 == 0) {
        const float NEG = -3.0e38f;
        int n0 = lane, n1 = lane + 32;
        bool v0ok = (n0 < cnt), v1ok = (n1 < cnt);
        float l0 = v0ok ? lg[b][n0] : NEG;
        float l1 = v1ok ? lg[b][n1] : NEG;
        float mx = fmaxf(l0, l1);
#pragma unroll
        for (int off = 16; off; off >>= 1)
            mx = fmaxf(mx, __shfl_xor_sync(0xffffffffu, mx, off));

        float br0 = br[0];
        float e0 = v0ok ? __expf(l0 - mx) : 0.0f;
        float e1 = v1ok ? __expf(l1 - mx) : 0.0f;
        // sr[n] = v[n] - v[n-1], v[-1] treated as 0 (pad); v includes br
        float vn0 = v0ok ? (g_V[b][n0] + br0) : 0.0f;
        float vp0 = (v0ok && n0 > 0) ? (g_V[b][n0 - 1] + br0) : 0.0f;
        float vn1 = v1ok ? (g_V[b][n1] + br0) : 0.0f;
        float vp1 = v1ok ? (g_V[b][n1 - 1] + br0) : 0.0f;   // n1-1 >= 31 >= 0
        float sum = e0 + e1;
        float rew = e0 * (vn0 - vp0) + e1 * (vn1 - vp1);
#pragma unroll
        for (int off = 16; off; off >>= 1) {
            sum += __shfl_xor_sync(0xffffffffu, sum, off);
            rew += __shfl_xor_sync(0xffffffffu, rew, off);
        }
        if (lane == 0) s_rew[b] = rew / sum;
    }
    __syncthreads();

    if (tid == 0) {
        float loss = 0.0f;
#pragma unroll
        for (int i = 0; i < 4; i++) {
            float x = s_rew[i] - s_rew[i + 4];
            loss += (x >= 0.0f) ? log1pf(expf(-x)) : (-x + log1pf(expf(x)));
        }
        loss *= 0.25f;
        if (out_size >= 9) {
            out[0] = loss;
            for (int i = 0; i < 8; i++) out[1 + i] = s_rew[i];
        } else if (out_size == 8) {
            for (int i = 0; i < 8; i++) out[i] = s_rew[i];
        } else {
            out[0] = loss;
        }
    }

    // ---- re-zero accumulators for the next replay (all reads are done) ----
    float4 z4 = make_float4(0.f, 0.f, 0.f, 0.f);
    float4* kz = (float4*)&g_K[0][0][0];
    for (int j = tid; j < BB * NMAX * DD / 4; j += 1024) kz[j] = z4;
    (&g_Q[0][0])[tid] = 0.0f;                 // BB*DD == 1024 exactly
    if (tid < BB * NMAX) (&g_V[0][0])[tid] = 0.0f;
}

// ---------------------------------------------------------------------------
extern "C" void kernel_launch(void* const* d_in, const int* in_sizes, int n_in,
                              void* d_out, int out_size) {
    const float* hid  = (const float*)d_in[0];
    const int*   mask = (const int*)  d_in[1];
    const float* Wq   = (const float*)d_in[2];
    const float* bq   = (const float*)d_in[3];
    const float* Wk   = (const float*)d_in[4];
    const float* bk   = (const float*)d_in[5];
    const float* Wr   = (const float*)d_in[6];
    const float* br   = (const float*)d_in[7];
    float* out = (float*)d_out;

    k_proj<<<dim3(NT, BB, SPL), TPB>>>(hid, mask, Wq, Wk, Wr);
    k_attn_loss<<<1, 1024>>>(mask, bq, bk, br, out, out_size);
}

// round 7
// speedup vs baseline: 1.7552x; 1.2330x over previous
#include <cuda_runtime.h>
#include <math.h>

#define BB 8
#define SS 4096
#define HH 4096
#define DD 128
#define NMAX 64
#define NT 64
#define HT 64            /* HH / NT */
#define TPB 128
#define SPL 2            /* row split */

// -------- persistent scratch: zero at module load; k_attn_loss re-zeros ----
__device__ float g_K[BB][NMAX][DD];   // 256 KB
__device__ float g_Q[BB][DD];
__device__ float g_V[BB][NMAX];
__device__ float g_rew[BB];
__device__ int   g_done;              // arrival counter (reset by block 0)

__device__ __forceinline__ void red_v2(float* p, float x, float y) {
    asm volatile("red.global.add.v2.f32 [%0], {%1,%2};"
                 :: "l"(p), "f"(x), "f"(y) : "memory");
}

// ---------------------------------------------------------------------------
// Kernel 1: projections at sentence rows. grid=(NT, B, SPL), 128 threads.
// (unchanged — fma/LDS-balanced)
// ---------------------------------------------------------------------------
__global__ void __launch_bounds__(TPB)
k_proj(const float* __restrict__ hid,
       const int*   __restrict__ mask,
       const float* __restrict__ Wq,
       const float* __restrict__ Wk,
       const float* __restrict__ Wr) {
    const int b     = blockIdx.y;
    const int tile  = blockIdx.x;
    const int split = blockIdx.z;
    const int h0    = tile * HT;
    const int tid   = threadIdx.x;
    const int lane  = tid & 31, warp = tid >> 5;

    __shared__ __align__(16) float sh[(NMAX / 2) * HT];   // 8 KB row tile
    __shared__ __align__(16) float sK[NMAX / 2][DD];      // 16 KB K staging
    __shared__ float swr[HT];
    __shared__ int   s_pos[NMAX];
    __shared__ int   s_wsum[4];
    __shared__ int   s_base;

    // ---- issue Wk register preload FIRST (overlaps the scan below) ----
    unsigned long long wk2[HT / 2];
#pragma unroll
    for (int j = 0; j < HT / 2; j++) {
        float w0 = Wk[(size_t)(h0 + 2 * j) * DD + tid];
        float w1 = Wk[(size_t)(h0 + 2 * j + 1) * DD + tid];
        asm("mov.b64 %0,{%1,%2};" : "=l"(wk2[j]) : "f"(w0), "f"(w1));
    }
    if (tid < HT) swr[tid] = Wr[h0 + tid];

    // ---- inline mask scan: 2 passes, int4 loads ----
    if (tid == 0) s_base = 0;
    __syncthreads();
    const int* mrow = mask + b * SS;
    for (int pass = 0; pass < 2; pass++) {
        int base = pass * (SS / 2) + tid * 16;
        const int4* m4 = (const int4*)(mrow + base);
        int v[16];
        { int4 t0 = m4[0], t1 = m4[1], t2 = m4[2], t3 = m4[3];
          v[0]=t0.x; v[1]=t0.y; v[2]=t0.z; v[3]=t0.w;
          v[4]=t1.x; v[5]=t1.y; v[6]=t1.z; v[7]=t1.w;
          v[8]=t2.x; v[9]=t2.y; v[10]=t2.z; v[11]=t2.w;
          v[12]=t3.x; v[13]=t3.y; v[14]=t3.z; v[15]=t3.w; }
        int c = 0;
#pragma unroll
        for (int j = 0; j < 16; j++) c += (v[j] > 0);
        int x = c;
#pragma unroll
        for (int off = 1; off < 32; off <<= 1) {
            int y = __shfl_up_sync(0xffffffffu, x, off);
            if (lane >= off) x += y;
        }
        if (lane == 31) s_wsum[warp] = x;
        __syncthreads();
        int r = s_base + x - c;
        for (int w = 0; w < warp; w++) r += s_wsum[w];
#pragma unroll
        for (int j = 0; j < 16; j++) {
            if (v[j] > 0) { if (r < NMAX) s_pos[r] = base + j; r++; }
        }
        __syncthreads();
        if (tid == 0) {
            int tot = s_base;
            for (int w = 0; w < 4; w++) tot += s_wsum[w];
            s_base = tot;
        }
        __syncthreads();
    }
    const int cnt  = (s_base < NMAX) ? s_base : NMAX;
    const int nloc = (cnt > split) ? ((cnt - split + 1) >> 1) : 0;

    // ---- preload this block's sentence-row slices into smem ----
    {
        int tot4 = nloc * (HT / 4);
        float4* sh4 = (float4*)sh;
        for (int i = tid; i < tot4; i += TPB) {
            int row = i >> 4;            // HT/4 = 16
            int c4  = i & 15;
            sh4[i] = *(const float4*)(hid +
                ((size_t)b * SS + s_pos[split + 2 * row]) * HH + h0 + c4 * 4);
        }
    }
    __syncthreads();

    // ---- mainloop: 2 rows per iteration, 4 independent FFMA2 chains ----
    int i = 0;
    for (; i + 2 <= nloc; i += 2) {
        const ulonglong2* r0 = (const ulonglong2*)&sh[i * HT];
        const ulonglong2* r1 = (const ulonglong2*)&sh[(i + 1) * HT];
        unsigned long long a00 = 0ull, a01 = 0ull, a10 = 0ull, a11 = 0ull;
#pragma unroll
        for (int j = 0; j < HT / 4; j++) {
            ulonglong2 x0 = r0[j], x1 = r1[j];
            asm("fma.rn.f32x2 %0,%1,%2,%0;" : "+l"(a00) : "l"(x0.x), "l"(wk2[2*j]));
            asm("fma.rn.f32x2 %0,%1,%2,%0;" : "+l"(a10) : "l"(x1.x), "l"(wk2[2*j]));
            asm("fma.rn.f32x2 %0,%1,%2,%0;" : "+l"(a01) : "l"(x0.y), "l"(wk2[2*j+1]));
            asm("fma.rn.f32x2 %0,%1,%2,%0;" : "+l"(a11) : "l"(x1.y), "l"(wk2[2*j+1]));
        }
        float l0,h0f,l1,h1f,l2,h2f,l3,h3f;
        asm("mov.b64 {%0,%1},%2;" : "=f"(l0), "=f"(h0f) : "l"(a00));
        asm("mov.b64 {%0,%1},%2;" : "=f"(l1), "=f"(h1f) : "l"(a01));
        asm("mov.b64 {%0,%1},%2;" : "=f"(l2), "=f"(h2f) : "l"(a10));
        asm("mov.b64 {%0,%1},%2;" : "=f"(l3), "=f"(h3f) : "l"(a11));
        sK[i][tid]     = (l0 + h0f) + (l1 + h1f);
        sK[i + 1][tid] = (l2 + h2f) + (l3 + h3f);

        if (tid < HT) {   // V partials for both rows (warps 0,1)
            float vp0 = sh[i * HT + tid] * swr[tid];
            float vp1 = sh[(i + 1) * HT + tid] * swr[tid];
#pragma unroll
            for (int off = 16; off; off >>= 1) {
                vp0 += __shfl_down_sync(0xffffffffu, vp0, off);
                vp1 += __shfl_down_sync(0xffffffffu, vp1, off);
            }
            if (lane == 0) {
                atomicAdd(&g_V[b][split + 2 * i], vp0);
                atomicAdd(&g_V[b][split + 2 * (i + 1)], vp1);
            }
        }
    }
    if (i < nloc) {       // odd tail row
        const ulonglong2* r0 = (const ulonglong2*)&sh[i * HT];
        unsigned long long a00 = 0ull, a01 = 0ull;
#pragma unroll
        for (int j = 0; j < HT / 4; j++) {
            ulonglong2 x0 = r0[j];
            asm("fma.rn.f32x2 %0,%1,%2,%0;" : "+l"(a00) : "l"(x0.x), "l"(wk2[2*j]));
            asm("fma.rn.f32x2 %0,%1,%2,%0;" : "+l"(a01) : "l"(x0.y), "l"(wk2[2*j+1]));
        }
        float l0,h0f,l1,h1f;
        asm("mov.b64 {%0,%1},%2;" : "=f"(l0), "=f"(h0f) : "l"(a00));
        asm("mov.b64 {%0,%1},%2;" : "=f"(l1), "=f"(h1f) : "l"(a01));
        sK[i][tid] = (l0 + h0f) + (l1 + h1f);
        if (tid < HT) {
            float vp0 = sh[i * HT + tid] * swr[tid];
#pragma unroll
            for (int off = 16; off; off >>= 1)
                vp0 += __shfl_down_sync(0xffffffffu, vp0, off);
            if (lane == 0) atomicAdd(&g_V[b][split + 2 * i], vp0);
        }
    }

    // ---- Q: only the owner of the last sentence row ----
    if (((cnt - 1) & 1) == split) {
        int il = (cnt - 1 - split) >> 1;
        const float* srow = &sh[il * HT];
        float aq0 = 0.0f, aq1 = 0.0f;
#pragma unroll
        for (int j = 0; j < HT; j += 2) {
            aq0 += srow[j]     * Wq[(size_t)(h0 + j) * DD + tid];
            aq1 += srow[j + 1] * Wq[(size_t)(h0 + j + 1) * DD + tid];
        }
        atomicAdd(&g_Q[b][tid], aq0 + aq1);
    }
    __syncthreads();

    // ---- flush staged K rows with vector REDs ----
    for (int j = tid; j < nloc * (DD / 2); j += TPB) {
        int row = j >> 6, dh = j & 63;
        float2 v = *(const float2*)&sK[row][2 * dh];
        red_v2(&g_K[b][split + 2 * row][2 * dh], v.x, v.y);
    }
}

// ---------------------------------------------------------------------------
// Kernel 2: fused RoPE + logits + softmax + reward, ONE BLOCK PER BATCH,
// plus device-side join: block 0 spins on an arrival counter, computes the
// pairwise loss, writes out, and resets the counter for the next replay.
// grid = BB, 256 threads.
// ---------------------------------------------------------------------------
__global__ void __launch_bounds__(256)
k_attn_loss(const int*   __restrict__ mask,
            const float* __restrict__ bq,
            const float* __restrict__ bk,
            const float* __restrict__ br,
            float* __restrict__ out, int out_size) {
    const int b    = blockIdx.x;
    const int tid  = threadIdx.x;
    const int lane = tid & 31, warp = tid >> 5;   // 8 warps

    __shared__ float qs[DD];
    __shared__ float lg[NMAX];
    __shared__ int   s_part[8];
    __shared__ int   s_cnt;

    // ---- count sentences: int4 loads, 4 per thread ----
    int c = 0;
    const int4* m4 = (const int4*)(mask + b * SS);
#pragma unroll
    for (int j = 0; j < 4; j++) {
        int4 m = m4[tid + j * 256];
        c += (m.x > 0) + (m.y > 0) + (m.z > 0) + (m.w > 0);
    }
#pragma unroll
    for (int off = 16; off; off >>= 1) c += __shfl_down_sync(0xffffffffu, c, off);
    if (lane == 0) s_part[warp] = c;
    __syncthreads();
    if (tid == 0) {
        int tot = 0;
#pragma unroll
        for (int w = 0; w < 8; w++) tot += s_part[w];
        s_cnt = (tot < NMAX) ? tot : NMAX;
    }
    __syncthreads();
    const int cnt = s_cnt;
    const int last = cnt - 1;

    const float LN_THETA = 9.210340371976184f;   // ln(10000)

    // ---- RoPE the single q row at rank = last (threads 0-127) ----
    if (tid < DD) {
        float freq = __expf(-LN_THETA * (float)(2 * (tid >> 1)) * (1.0f / 128.0f));
        float qv = g_Q[b][tid] + bq[tid];
        float a = (float)last * freq;
        float cq = __cosf(a), sq = __sinf(a);
        float qp = __shfl_xor_sync(0xffffffffu, qv, 1);
        qs[tid] = ((tid & 1) == 0) ? (qv * cq - qp * sq) : (qp * sq + qv * cq);
    }
    __syncthreads();

    // ---- logits: warp w handles n = w, w+8, ... (~5 iterations) ----
    float fr[4];
#pragma unroll
    for (int s4 = 0; s4 < 4; s4++) {
        int d = lane + s4 * 32;
        fr[s4] = __expf(-LN_THETA * (float)(2 * (d >> 1)) * (1.0f / 128.0f));
    }
    for (int n = warp; n < cnt; n += 8) {
        float dot = 0.0f;
        float nf = (float)n;
#pragma unroll
        for (int s4 = 0; s4 < 4; s4++) {
            int d = lane + s4 * 32;
            float kv = g_K[b][n][d] + bk[d];
            float a = nf * fr[s4];
            float cn = __cosf(a), sn = __sinf(a);
            float kp = __shfl_xor_sync(0xffffffffu, kv, 1);
            float kr = ((d & 1) == 0) ? (kv * cn - kp * sn) : (kp * sn + kv * cn);
            dot += qs[d] * kr;
        }
#pragma unroll
        for (int off = 16; off; off >>= 1)
            dot += __shfl_xor_sync(0xffffffffu, dot, off);
        if (lane == 0) lg[n] = dot * 0.08838834764831845f;  // 1/sqrt(128)
    }
    __syncthreads();

    // ---- warp-parallel softmax + reward: warp 0 ----
    if (warp == 0) {
        const float NEG = -3.0e38f;
        int n0 = lane, n1 = lane + 32;
        bool v0ok = (n0 < cnt), v1ok = (n1 < cnt);
        float l0 = v0ok ? lg[n0] : NEG;
        float l1 = v1ok ? lg[n1] : NEG;
        float mx = fmaxf(l0, l1);
#pragma unroll
        for (int off = 16; off; off >>= 1)
            mx = fmaxf(mx, __shfl_xor_sync(0xffffffffu, mx, off));

        float br0 = br[0];
        float e0 = v0ok ? __expf(l0 - mx) : 0.0f;
        float e1 = v1ok ? __expf(l1 - mx) : 0.0f;
        float vn0 = v0ok ? (g_V[b][n0] + br0) : 0.0f;
        float vp0 = (v0ok && n0 > 0) ? (g_V[b][n0 - 1] + br0) : 0.0f;
        float vn1 = v1ok ? (g_V[b][n1] + br0) : 0.0f;
        float vp1 = v1ok ? (g_V[b][n1 - 1] + br0) : 0.0f;
        float sum = e0 + e1;
        float rew = e0 * (vn0 - vp0) + e1 * (vn1 - vp1);
#pragma unroll
        for (int off = 16; off; off >>= 1) {
            sum += __shfl_xor_sync(0xffffffffu, sum, off);
            rew += __shfl_xor_sync(0xffffffffu, rew, off);
        }
        if (lane == 0) {
            g_rew[b] = rew / sum;
            __threadfence();
            atomicAdd(&g_done, 1);      // announce this batch is ready
        }
    }

    // ---- re-zero this batch's accumulator slices (overlaps the join) ----
    {
        float4 z4 = make_float4(0.f, 0.f, 0.f, 0.f);
        float4* kz = (float4*)&g_K[b][0][0];
#pragma unroll
        for (int j = 0; j < NMAX * DD / 4 / 256; j++)   // 8 iterations
            kz[tid + j * 256] = z4;
        if (tid < DD)   g_Q[b][tid] = 0.0f;
        if (tid < NMAX) g_V[b][tid] = 0.0f;
    }

    // ---- block 0: join, pairwise loss, output, reset counter ----
    if (b == 0 && tid == 0) {
        while (atomicAdd(&g_done, 0) < BB) ;   // all 8 blocks co-resident
        __threadfence();
        float r[BB];
#pragma unroll
        for (int i = 0; i < BB; i++) r[i] = g_rew[i];
        float loss = 0.0f;
#pragma unroll
        for (int i = 0; i < 4; i++) {
            float x = r[i] - r[i + 4];
            loss += (x >= 0.0f) ? log1pf(expf(-x)) : (-x + log1pf(expf(x)));
        }
        loss *= 0.25f;
        if (out_size >= 9) {
            out[0] = loss;
            for (int i = 0; i < 8; i++) out[1 + i] = r[i];
        } else if (out_size == 8) {
            for (int i = 0; i < 8; i++) out[i] = r[i];
        } else {
            out[0] = loss;
        }
        g_done = 0;                     // reset for next graph replay
    }
}

// ---------------------------------------------------------------------------
extern "C" void kernel_launch(void* const* d_in, const int* in_sizes, int n_in,
                              void* d_out, int out_size) {
    const float* hid  = (const float*)d_in[0];
    const int*   mask = (const int*)  d_in[1];
    const float* Wq   = (const float*)d_in[2];
    const float* bq   = (const float*)d_in[3];
    const float* Wk   = (const float*)d_in[4];
    const float* bk   = (const float*)d_in[5];
    const float* Wr   = (const float*)d_in[6];
    const float* br   = (const float*)d_in[7];
    float* out = (float*)d_out;

    k_proj<<<dim3(NT, BB, SPL), TPB>>>(hid, mask, Wq, Wk, Wr);
    k_attn_loss<<<BB, 256>>>(mask, bq, bk, br, out, out_size);
}

// round 8
// speedup vs baseline: 1.8814x; 1.0719x over previous
#include <cuda_runtime.h>
#include <math.h>

#define BB 8
#define SS 4096
#define HH 4096
#define DD 128
#define NMAX 64
#define NT 64
#define HT 64            /* HH / NT */
#define TPB 128

// -------- persistent scratch: zero at load; attn tail re-zeros each replay --
__device__ float g_K[BB][NMAX][DD];   // 256 KB
__device__ float g_Q[BB][DD];
__device__ float g_V[BB][NMAX];
__device__ float g_rew[BB];
__device__ int   g_arrive[BB];        // per-batch arrival counters
__device__ int   g_done;              // cross-batch arrival counter

__device__ __forceinline__ void red_f32(float* p, float v) {
    asm volatile("red.global.add.f32 [%0], %1;" :: "l"(p), "f"(v) : "memory");
}

// ---------------------------------------------------------------------------
// ONE fused kernel. grid=(NT, BB), 128 threads.
// Phase 1 (all 512 blocks): h-sliced projections, RED into g_K/g_Q/g_V.
// Phase 2 (last block per batch): attention + reward + accumulator re-zero.
// Phase 3 (last batch): pairwise loss + output.
// ---------------------------------------------------------------------------
__global__ void __launch_bounds__(TPB)
k_fused(const float* __restrict__ hid,
        const int*   __restrict__ mask,
        const float* __restrict__ Wq,
        const float* __restrict__ bq,
        const float* __restrict__ Wk,
        const float* __restrict__ bk,
        const float* __restrict__ Wr,
        const float* __restrict__ br,
        float* __restrict__ out, int out_size) {
    const int b    = blockIdx.y;
    const int tile = blockIdx.x;
    const int h0   = tile * HT;
    const int tid  = threadIdx.x;
    const int lane = tid & 31, warp = tid >> 5;

    __shared__ __align__(16) float buf[NMAX * DD];  // 32KB: proj uses 16KB, attn all
    __shared__ float swr[HT];
    __shared__ float qs[DD];
    __shared__ float lg[NMAX];
    __shared__ float sv[NMAX];
    __shared__ int   s_pos[NMAX];
    __shared__ int   s_wsum[4];
    __shared__ int   s_base;
    __shared__ int   s_last;

    // ---- issue Wk register preload FIRST (overlaps the scan below) ----
    unsigned long long wk2[HT / 2];
#pragma unroll
    for (int j = 0; j < HT / 2; j++) {
        float w0 = Wk[(size_t)(h0 + 2 * j) * DD + tid];
        float w1 = Wk[(size_t)(h0 + 2 * j + 1) * DD + tid];
        asm("mov.b64 %0,{%1,%2};" : "=l"(wk2[j]) : "f"(w0), "f"(w1));
    }
    if (tid < HT) swr[tid] = Wr[h0 + tid];

    // ---- inline mask scan: 2 passes, int4 loads ----
    if (tid == 0) s_base = 0;
    __syncthreads();
    const int* mrow = mask + b * SS;
    for (int pass = 0; pass < 2; pass++) {
        int base = pass * (SS / 2) + tid * 16;
        const int4* m4 = (const int4*)(mrow + base);
        int v[16];
        { int4 t0 = m4[0], t1 = m4[1], t2 = m4[2], t3 = m4[3];
          v[0]=t0.x; v[1]=t0.y; v[2]=t0.z; v[3]=t0.w;
          v[4]=t1.x; v[5]=t1.y; v[6]=t1.z; v[7]=t1.w;
          v[8]=t2.x; v[9]=t2.y; v[10]=t2.z; v[11]=t2.w;
          v[12]=t3.x; v[13]=t3.y; v[14]=t3.z; v[15]=t3.w; }
        int c = 0;
#pragma unroll
        for (int j = 0; j < 16; j++) c += (v[j] > 0);
        int x = c;
#pragma unroll
        for (int off = 1; off < 32; off <<= 1) {
            int y = __shfl_up_sync(0xffffffffu, x, off);
            if (lane >= off) x += y;
        }
        if (lane == 31) s_wsum[warp] = x;
        __syncthreads();
        int r = s_base + x - c;
        for (int w = 0; w < warp; w++) r += s_wsum[w];
#pragma unroll
        for (int j = 0; j < 16; j++) {
            if (v[j] > 0) { if (r < NMAX) s_pos[r] = base + j; r++; }
        }
        __syncthreads();
        if (tid == 0) {
            int tot = s_base;
            for (int w = 0; w < 4; w++) tot += s_wsum[w];
            s_base = tot;
        }
        __syncthreads();
    }
    const int cnt  = (s_base < NMAX) ? s_base : NMAX;
    const int last = cnt - 1;

    // ---- preload ALL sentence-row slices into smem (one MLP burst) ----
    {
        int tot4 = cnt * (HT / 4);
        float4* b4 = (float4*)buf;
        for (int i = tid; i < tot4; i += TPB) {
            int row = i >> 4;            // HT/4 = 16
            int c4  = i & 15;
            b4[i] = *(const float4*)(hid +
                ((size_t)b * SS + s_pos[row]) * HH + h0 + c4 * 4);
        }
    }
    __syncthreads();

    // ---- mainloop: 2 rows/iter, 4 FFMA2 chains, direct RED flush ----
    int i = 0;
    for (; i + 2 <= cnt; i += 2) {
        const ulonglong2* r0 = (const ulonglong2*)&buf[i * HT];
        const ulonglong2* r1 = (const ulonglong2*)&buf[(i + 1) * HT];
        unsigned long long a00 = 0ull, a01 = 0ull, a10 = 0ull, a11 = 0ull;
#pragma unroll
        for (int j = 0; j < HT / 4; j++) {
            ulonglong2 x0 = r0[j], x1 = r1[j];
            asm("fma.rn.f32x2 %0,%1,%2,%0;" : "+l"(a00) : "l"(x0.x), "l"(wk2[2*j]));
            asm("fma.rn.f32x2 %0,%1,%2,%0;" : "+l"(a10) : "l"(x1.x), "l"(wk2[2*j]));
            asm("fma.rn.f32x2 %0,%1,%2,%0;" : "+l"(a01) : "l"(x0.y), "l"(wk2[2*j+1]));
            asm("fma.rn.f32x2 %0,%1,%2,%0;" : "+l"(a11) : "l"(x1.y), "l"(wk2[2*j+1]));
        }
        float l0,h0f,l1,h1f,l2,h2f,l3,h3f;
        asm("mov.b64 {%0,%1},%2;" : "=f"(l0), "=f"(h0f) : "l"(a00));
        asm("mov.b64 {%0,%1},%2;" : "=f"(l1), "=f"(h1f) : "l"(a01));
        asm("mov.b64 {%0,%1},%2;" : "=f"(l2), "=f"(h2f) : "l"(a10));
        asm("mov.b64 {%0,%1},%2;" : "=f"(l3), "=f"(h3f) : "l"(a11));
        red_f32(&g_K[b][i][tid],     (l0 + h0f) + (l1 + h1f));
        red_f32(&g_K[b][i + 1][tid], (l2 + h2f) + (l3 + h3f));

        if (tid < HT) {   // V partials for both rows (warps 0,1 each cover 32 h)
            float vp0 = buf[i * HT + tid] * swr[tid];
            float vp1 = buf[(i + 1) * HT + tid] * swr[tid];
#pragma unroll
            for (int off = 16; off; off >>= 1) {
                vp0 += __shfl_down_sync(0xffffffffu, vp0, off);
                vp1 += __shfl_down_sync(0xffffffffu, vp1, off);
            }
            if (lane == 0) {
                red_f32(&g_V[b][i], vp0);
                red_f32(&g_V[b][i + 1], vp1);
            }
        }
    }
    if (i < cnt) {       // odd tail row
        const ulonglong2* r0 = (const ulonglong2*)&buf[i * HT];
        unsigned long long a00 = 0ull, a01 = 0ull;
#pragma unroll
        for (int j = 0; j < HT / 4; j++) {
            ulonglong2 x0 = r0[j];
            asm("fma.rn.f32x2 %0,%1,%2,%0;" : "+l"(a00) : "l"(x0.x), "l"(wk2[2*j]));
            asm("fma.rn.f32x2 %0,%1,%2,%0;" : "+l"(a01) : "l"(x0.y), "l"(wk2[2*j+1]));
        }
        float l0,h0f,l1,h1f;
        asm("mov.b64 {%0,%1},%2;" : "=f"(l0), "=f"(h0f) : "l"(a00));
        asm("mov.b64 {%0,%1},%2;" : "=f"(l1), "=f"(h1f) : "l"(a01));
        red_f32(&g_K[b][i][tid], (l0 + h0f) + (l1 + h1f));
        if (tid < HT) {
            float vp0 = buf[i * HT + tid] * swr[tid];
#pragma unroll
            for (int off = 16; off; off >>= 1)
                vp0 += __shfl_down_sync(0xffffffffu, vp0, off);
            if (lane == 0) red_f32(&g_V[b][i], vp0);
        }
    }

    // ---- Q: every block contributes its h-slice of the last sentence row ----
    {
        const float* srow = &buf[last * HT];
        float aq0 = 0.0f, aq1 = 0.0f;
#pragma unroll
        for (int j = 0; j < HT; j += 2) {
            aq0 += srow[j]     * Wq[(size_t)(h0 + j) * DD + tid];
            aq1 += srow[j + 1] * Wq[(size_t)(h0 + j + 1) * DD + tid];
        }
        red_f32(&g_Q[b][tid], aq0 + aq1);
    }

    // ---- arrival: last block of this batch proceeds to attention ----
    __threadfence();
    __syncthreads();
    if (tid == 0) {
        int old = atomicAdd(&g_arrive[b], 1);
        s_last = (old == NT - 1);
        if (s_last) g_arrive[b] = 0;     // reset for next replay
    }
    __syncthreads();
    if (!s_last) return;
    __threadfence();                     // acquire: make all REDs visible

    // =================== attention tail (1 block per batch) ================
    // burst g_K[b] into smem; zero it behind the read
    {
        float4* b4 = (float4*)buf;
        float4 z = make_float4(0.f, 0.f, 0.f, 0.f);
        int tot = cnt * (DD / 4);
        for (int ii = tid; ii < tot; ii += TPB) {
            int row = ii >> 5, c4 = ii & 31;
            float4 v = *(const float4*)&g_K[b][row][c4 * 4];
            b4[ii] = v;
            *(float4*)&g_K[b][row][c4 * 4] = z;
        }
    }
    if (tid < NMAX) { sv[tid] = g_V[b][tid]; g_V[b][tid] = 0.0f; }

    const float LN_THETA = 9.210340371976184f;   // ln(10000)

    // RoPE the single q row at rank = last; zero g_Q behind the read
    {
        float freq = __expf(-LN_THETA * (float)(2 * (tid >> 1)) * (1.0f / 128.0f));
        float qv = g_Q[b][tid] + bq[tid];
        g_Q[b][tid] = 0.0f;
        float a = (float)last * freq;
        float cq = __cosf(a), sq = __sinf(a);
        float qp = __shfl_xor_sync(0xffffffffu, qv, 1);
        qs[tid] = ((tid & 1) == 0) ? (qv * cq - qp * sq) : (qp * sq + qv * cq);
    }
    __syncthreads();

    // logits from smem: warp w handles n = w, w+4, ...
    float fr[4];
#pragma unroll
    for (int s4 = 0; s4 < 4; s4++) {
        int d = lane + s4 * 32;
        fr[s4] = __expf(-LN_THETA * (float)(2 * (d >> 1)) * (1.0f / 128.0f));
    }
    for (int n = warp; n < cnt; n += 4) {
        float dot = 0.0f;
        float nf = (float)n;
#pragma unroll
        for (int s4 = 0; s4 < 4; s4++) {
            int d = lane + s4 * 32;
            float kv = buf[n * DD + d] + bk[d];
            float a = nf * fr[s4];
            float cn = __cosf(a), sn = __sinf(a);
            float kp = __shfl_xor_sync(0xffffffffu, kv, 1);
            float kr = ((d & 1) == 0) ? (kv * cn - kp * sn) : (kp * sn + kv * cn);
            dot += qs[d] * kr;
        }
#pragma unroll
        for (int off = 16; off; off >>= 1)
            dot += __shfl_xor_sync(0xffffffffu, dot, off);
        if (lane == 0) lg[n] = dot * 0.08838834764831845f;  // 1/sqrt(128)
    }
    __syncthreads();

    // warp-parallel softmax + reward; then cross-batch join + loss
    if (warp == 0) {
        const float NEG = -3.0e38f;
        int n0 = lane, n1 = lane + 32;
        bool v0ok = (n0 < cnt), v1ok = (n1 < cnt);
        float l0 = v0ok ? lg[n0] : NEG;
        float l1 = v1ok ? lg[n1] : NEG;
        float mx = fmaxf(l0, l1);
#pragma unroll
        for (int off = 16; off; off >>= 1)
            mx = fmaxf(mx, __shfl_xor_sync(0xffffffffu, mx, off));

        float br0 = br[0];
        float e0 = v0ok ? __expf(l0 - mx) : 0.0f;
        float e1 = v1ok ? __expf(l1 - mx) : 0.0f;
        float vn0 = v0ok ? (sv[n0] + br0) : 0.0f;
        float vp0 = (v0ok && n0 > 0) ? (sv[n0 - 1] + br0) : 0.0f;
        float vn1 = v1ok ? (sv[n1] + br0) : 0.0f;
        float vp1 = v1ok ? (sv[n1 - 1] + br0) : 0.0f;
        float sum = e0 + e1;
        float rew = e0 * (vn0 - vp0) + e1 * (vn1 - vp1);
#pragma unroll
        for (int off = 16; off; off >>= 1) {
            sum += __shfl_xor_sync(0xffffffffu, sum, off);
            rew += __shfl_xor_sync(0xffffffffu, rew, off);
        }
        if (lane == 0) {
            g_rew[b] = rew / sum;
            __threadfence();
            int old2 = atomicAdd(&g_done, 1);
            if (old2 == BB - 1) {        // last batch: pairwise loss + output
                __threadfence();
                float r[BB];
#pragma unroll
                for (int k = 0; k < BB; k++) r[k] = g_rew[k];
                float loss = 0.0f;
#pragma unroll
                for (int k = 0; k < 4; k++) {
                    float x = r[k] - r[k + 4];
                    loss += (x >= 0.0f) ? log1pf(expf(-x))
                                        : (-x + log1pf(expf(x)));
                }
                loss *= 0.25f;
                if (out_size >= 9) {
                    out[0] = loss;
                    for (int k = 0; k < 8; k++) out[1 + k] = r[k];
                } else if (out_size == 8) {
                    for (int k = 0; k < 8; k++) out[k] = r[k];
                } else {
                    out[0] = loss;
                }
                g_done = 0;              // reset for next replay
            }
        }
    }
}

// ---------------------------------------------------------------------------
extern "C" void kernel_launch(void* const* d_in, const int* in_sizes, int n_in,
                              void* d_out, int out_size) {
    const float* hid  = (const float*)d_in[0];
    const int*   mask = (const int*)  d_in[1];
    const float* Wq   = (const float*)d_in[2];
    const float* bq   = (const float*)d_in[3];
    const float* Wk   = (const float*)d_in[4];
    const float* bk   = (const float*)d_in[5];
    const float* Wr   = (const float*)d_in[6];
    const float* br   = (const float*)d_in[7];
    float* out = (float*)d_out;

    k_fused<<<dim3(NT, BB), TPB>>>(hid, mask, Wq, bq, Wk, bk, Wr, br,
                                   out, out_size);
}